// round 1
// baseline (speedup 1.0000x reference)
#include <cuda_runtime.h>
#include <math.h>

#define H1H 2048          // hidden size for both layers
#define VOC 50257

// Scratch (no allocations allowed)
__device__ float g_h1n[H1H];
__device__ float g_h2n[H1H];
__device__ float g_logits[VOC];
__device__ float g_stats[2];   // [0]=max, [1]=log(sum exp)

// ---------------------------------------------------------------------------
// Fused LSTM layer: one block per hidden unit. Block computes the 4 gate
// dot-products (rows r, r+H, r+2H, r+3H of W_ih and W_hh) against x/h staged
// in shared memory, then applies the LSTM nonlinearity and writes h_new[r].
// Every weight element is read exactly once (float4 vectorized).
// ---------------------------------------------------------------------------
__global__ __launch_bounds__(256) void lstm_layer_kernel(
    const float* __restrict__ Wih, const float* __restrict__ Whh,
    const float* __restrict__ bih, const float* __restrict__ bhh,
    const float* __restrict__ x,  const float* __restrict__ h,
    const float* __restrict__ c,  float* __restrict__ hout, int nx)
{
    __shared__ float sx[2048];
    __shared__ float sh[2048];
    __shared__ float sred[4 * 8];

    const int tid = threadIdx.x;
    for (int i = tid; i < nx;  i += 256) sx[i] = x[i];
    for (int i = tid; i < H1H; i += 256) sh[i] = h[i];
    __syncthreads();

    const int r = blockIdx.x;               // hidden unit index 0..H-1
    const int nx4 = nx >> 2;
    const float4* sx4 = (const float4*)sx;
    const float4* sh4 = (const float4*)sh;

    float acc[4];
    #pragma unroll
    for (int g = 0; g < 4; g++) {
        const size_t row = (size_t)(r + g * H1H);
        const float4* wi = (const float4*)(Wih + row * (size_t)nx);
        const float4* wh = (const float4*)(Whh + row * (size_t)H1H);
        float a = 0.0f;
        for (int j = tid; j < nx4; j += 256) {
            float4 wv = wi[j]; float4 xv = sx4[j];
            a += wv.x * xv.x + wv.y * xv.y + wv.z * xv.z + wv.w * xv.w;
        }
        for (int j = tid; j < (H1H >> 2); j += 256) {
            float4 wv = wh[j]; float4 hv = sh4[j];
            a += wv.x * hv.x + wv.y * hv.y + wv.z * hv.z + wv.w * hv.w;
        }
        acc[g] = a;
    }

    // warp-shuffle reduce, then per-warp partials to shared
    #pragma unroll
    for (int g = 0; g < 4; g++) {
        float a = acc[g];
        #pragma unroll
        for (int o = 16; o > 0; o >>= 1)
            a += __shfl_down_sync(0xffffffffu, a, o);
        if ((tid & 31) == 0) sred[g * 8 + (tid >> 5)] = a;
    }
    __syncthreads();

    if (tid == 0) {
        float gi = 0.f, gf = 0.f, gg = 0.f, go = 0.f;
        #pragma unroll
        for (int w = 0; w < 8; w++) {
            gi += sred[0 * 8 + w];
            gf += sred[1 * 8 + w];
            gg += sred[2 * 8 + w];
            go += sred[3 * 8 + w];
        }
        gi += bih[r]           + bhh[r];
        gf += bih[r + H1H]     + bhh[r + H1H];
        gg += bih[r + 2 * H1H] + bhh[r + 2 * H1H];
        go += bih[r + 3 * H1H] + bhh[r + 3 * H1H];

        const float iv = 1.0f / (1.0f + expf(-gi));
        const float fv = 1.0f / (1.0f + expf(-gf));
        const float gv = tanhf(gg);
        const float ov = 1.0f / (1.0f + expf(-go));
        const float cn = fv * c[r] + iv * gv;
        hout[r] = ov * tanhf(cn);
    }
}

// ---------------------------------------------------------------------------
// Vocab projection: one warp per vocab row, h2n in shared. 16 independent
// float4 loads per lane per row -> deep MLP against DRAM latency.
// ---------------------------------------------------------------------------
__global__ __launch_bounds__(256) void vocab_kernel(
    const float* __restrict__ W, const float* __restrict__ b,
    const float* __restrict__ h, float* __restrict__ logits)
{
    __shared__ float sh[2048];
    const int tid = threadIdx.x;
    for (int i = tid; i < 2048; i += 256) sh[i] = h[i];
    __syncthreads();

    const int warp = blockIdx.x * 8 + (tid >> 5);
    const int lane = tid & 31;
    if (warp >= VOC) return;

    const float4* w4  = (const float4*)(W + (size_t)warp * 2048);
    const float4* sh4 = (const float4*)sh;
    float a = 0.0f;
    #pragma unroll
    for (int j = lane; j < 512; j += 32) {
        float4 wv = w4[j]; float4 hv = sh4[j];
        a += wv.x * hv.x + wv.y * hv.y + wv.z * hv.z + wv.w * hv.w;
    }
    #pragma unroll
    for (int o = 16; o > 0; o >>= 1)
        a += __shfl_down_sync(0xffffffffu, a, o);
    if (lane == 0) logits[warp] = a + b[warp];
}

// ---------------------------------------------------------------------------
// Single-block one-pass online logsumexp over the 50257 logits (L2 resident).
// ---------------------------------------------------------------------------
__global__ __launch_bounds__(1024) void lse_kernel(const float* __restrict__ logits)
{
    __shared__ float sm[1024];
    __shared__ float ss[1024];
    const int tid = threadIdx.x;

    float m = -INFINITY, s = 0.0f;
    for (int i = tid; i < VOC; i += 1024) {
        const float v = logits[i];
        const float nm = fmaxf(m, v);
        s = s * expf(m - nm) + expf(v - nm);
        m = nm;
    }
    sm[tid] = m; ss[tid] = s;
    __syncthreads();
    for (int stride = 512; stride > 0; stride >>= 1) {
        if (tid < stride) {
            const float m2 = sm[tid + stride], s2 = ss[tid + stride];
            const float nm = fmaxf(m, m2);
            s = s * expf(m - nm) + s2 * expf(m2 - nm);
            m = nm;
            sm[tid] = m; ss[tid] = s;
        }
        __syncthreads();
    }
    if (tid == 0) { g_stats[0] = m; g_stats[1] = logf(s); }
}

__global__ __launch_bounds__(256) void finalize_kernel(
    const float* __restrict__ logits, float* __restrict__ out)
{
    const int i = blockIdx.x * 256 + threadIdx.x;
    if (i < VOC) out[i] = logits[i] - g_stats[0] - g_stats[1];
}

// ---------------------------------------------------------------------------
extern "C" void kernel_launch(void* const* d_in, const int* in_sizes, int n_in,
                              void* d_out, int out_size)
{
    const float* x     = (const float*)d_in[0];
    const float* h1    = (const float*)d_in[1];
    const float* c1    = (const float*)d_in[2];
    const float* h2    = (const float*)d_in[3];
    const float* c2    = (const float*)d_in[4];
    const float* W_ih1 = (const float*)d_in[5];
    const float* W_hh1 = (const float*)d_in[6];
    const float* b_ih1 = (const float*)d_in[7];
    const float* b_hh1 = (const float*)d_in[8];
    const float* W_ih2 = (const float*)d_in[9];
    const float* W_hh2 = (const float*)d_in[10];
    const float* b_ih2 = (const float*)d_in[11];
    const float* b_hh2 = (const float*)d_in[12];
    const float* W_out = (const float*)d_in[13];
    const float* b_out = (const float*)d_in[14];
    float* out = (float*)d_out;

    float* h1n;    cudaGetSymbolAddress((void**)&h1n,    g_h1n);
    float* h2n;    cudaGetSymbolAddress((void**)&h2n,    g_h2n);
    float* logits; cudaGetSymbolAddress((void**)&logits, g_logits);

    // Layer 1: x[1024], h1/c1[2048]
    lstm_layer_kernel<<<H1H, 256>>>(W_ih1, W_hh1, b_ih1, b_hh1,
                                    x, h1, c1, h1n, 1024);
    // Layer 2: input = h1n[2048]
    lstm_layer_kernel<<<H1H, 256>>>(W_ih2, W_hh2, b_ih2, b_hh2,
                                    h1n, h2, c2, h2n, 2048);
    // Vocab projection
    vocab_kernel<<<(VOC + 7) / 8, 256>>>(W_out, b_out, h2n, logits);
    // log-softmax
    lse_kernel<<<1, 1024>>>(logits);
    finalize_kernel<<<(VOC + 255) / 256, 256>>>(logits, out);
}